// round 1
// baseline (speedup 1.0000x reference)
#include <cuda_runtime.h>

#define B_ROWS   8192
#define N_DIM    2048
#define K_DIM    64
#define M_TILE   64
#define NC       32           // n-values per SMEM chunk
#define NCHUNKS  (N_DIM / NC) // 64
#define THREADS  128
#define XS_STRIDE 36          // 32 + pad; multiple of 4 for 16B-aligned rows

// Precomputed s[n] = sum_k v[n,k]^2
__device__ float g_s[N_DIM];

__global__ void precompute_s_kernel(const float* __restrict__ v) {
    int n = blockIdx.x * blockDim.x + threadIdx.x;
    if (n < N_DIM) {
        const float4* row = reinterpret_cast<const float4*>(v + (size_t)n * K_DIM);
        float acc = 0.0f;
#pragma unroll
        for (int i = 0; i < K_DIM / 4; i++) {
            float4 q = row[i];
            acc = fmaf(q.x, q.x, acc);
            acc = fmaf(q.y, q.y, acc);
            acc = fmaf(q.z, q.z, acc);
            acc = fmaf(q.w, q.w, acc);
        }
        g_s[n] = acc;
    }
}

__device__ __forceinline__ unsigned long long pack2(float lo, float hi) {
    unsigned long long r;
    asm("mov.b64 %0, {%1, %2};" : "=l"(r) : "f"(lo), "f"(hi));
    return r;
}
__device__ __forceinline__ unsigned long long packdup(float x) {
    unsigned long long r;
    asm("mov.b64 %0, {%1, %1};" : "=l"(r) : "f"(x));
    return r;
}
__device__ __forceinline__ void unpack2(unsigned long long a, float& lo, float& hi) {
    asm("mov.b64 {%0, %1}, %2;" : "=f"(lo), "=f"(hi) : "l"(a));
}
__device__ __forceinline__ void fma2(unsigned long long& d, unsigned long long a,
                                     unsigned long long b) {
    asm("fma.rn.f32x2 %0, %1, %2, %0;" : "+l"(d) : "l"(a), "l"(b));
}

__global__ void __launch_bounds__(THREADS, 1)
fm_kernel(const float* __restrict__ x, const float* __restrict__ v,
          float* __restrict__ out) {
    __shared__ float Xs[M_TILE * XS_STRIDE];  // [row][n_local], 9216 B
    __shared__ float Vs[NC * K_DIM];          // [kk][k] linear, 8192 B
    __shared__ float Ss[NC];

    const int t   = threadIdx.x;
    const int tx  = t & 15;   // col group: cols tx*4 .. tx*4+3
    const int ty  = t >> 4;   // row group 0..7: rows ty*8 .. ty*8+7
    const int row0 = blockIdx.x * M_TILE;

    // accumulators: 8 rows x 4 cols, packed as col-pairs (f32x2)
    unsigned long long acc2[8][2];
#pragma unroll
    for (int r = 0; r < 8; r++) { acc2[r][0] = 0ull; acc2[r][1] = 0ull; }
    float t2acc[8];
#pragma unroll
    for (int r = 0; r < 8; r++) t2acc[r] = 0.0f;

    // ---- prefetch chunk 0 into registers ----
    float4 px[4], pv[4];
    float ps = 0.0f;
    {
        const int n0 = 0;
#pragma unroll
        for (int i = 0; i < 4; i++) {
            int j = t + i * THREADS;       // float4 index in tile (0..511)
            int row = j >> 3;
            int a = j & 7;
            px[i] = *reinterpret_cast<const float4*>(
                x + (size_t)(row0 + row) * N_DIM + n0 + 4 * a);
            pv[i] = *reinterpret_cast<const float4*>(
                v + (size_t)n0 * K_DIM + 4 * (size_t)j);
        }
        if (t < NC) ps = g_s[n0 + t];
    }

    for (int c = 0; c < NCHUNKS; c++) {
        // ---- stage registers -> SMEM ----
#pragma unroll
        for (int i = 0; i < 4; i++) {
            int j = t + i * THREADS;
            int row = j >> 3;
            int a = j & 7;
            *reinterpret_cast<float4*>(&Xs[row * XS_STRIDE + 4 * a]) = px[i];
            *reinterpret_cast<float4*>(&Vs[4 * j]) = pv[i];
        }
        if (t < NC) Ss[t] = ps;
        __syncthreads();

        // ---- prefetch next chunk (overlaps compute) ----
        if (c + 1 < NCHUNKS) {
            const int n0 = (c + 1) * NC;
#pragma unroll
            for (int i = 0; i < 4; i++) {
                int j = t + i * THREADS;
                int row = j >> 3;
                int a = j & 7;
                px[i] = *reinterpret_cast<const float4*>(
                    x + (size_t)(row0 + row) * N_DIM + n0 + 4 * a);
                pv[i] = *reinterpret_cast<const float4*>(
                    v + (size_t)n0 * K_DIM + 4 * (size_t)j);
            }
            if (t < NC) ps = g_s[n0 + t];
        }

        // ---- main MAC loop over this chunk ----
#pragma unroll 8
        for (int kk = 0; kk < NC; kk++) {
            float4 vf = *reinterpret_cast<const float4*>(&Vs[kk * K_DIM + tx * 4]);
            unsigned long long vd0 = pack2(vf.x, vf.y);
            unsigned long long vd1 = pack2(vf.z, vf.w);
#pragma unroll
            for (int r = 0; r < 8; r++) {
                float xv = Xs[(ty * 8 + r) * XS_STRIDE + kk];
                unsigned long long xd = packdup(xv);
                fma2(acc2[r][0], xd, vd0);
                fma2(acc2[r][1], xd, vd1);
            }
        }

        // ---- t2 term: this thread covers kk in {2tx, 2tx+1} ----
#pragma unroll
        for (int d = 0; d < 2; d++) {
            int kk = 2 * tx + d;
            float sv = Ss[kk];
#pragma unroll
            for (int r = 0; r < 8; r++) {
                float xv = Xs[(ty * 8 + r) * XS_STRIDE + kk];
                t2acc[r] = fmaf(xv * xv, sv, t2acc[r]);
            }
        }
        __syncthreads();
    }

    // ---- epilogue: per-row reduction across the 16 col-groups ----
    float* red1 = Xs;                 // 64*16 floats = 1024, fits in Xs
    float* red2 = Vs;                 // fits in Vs
#pragma unroll
    for (int r = 0; r < 8; r++) {
        float a, b, cc, dd;
        unpack2(acc2[r][0], a, b);
        unpack2(acc2[r][1], cc, dd);
        float cp = a * a + b * b + cc * cc + dd * dd;
        red1[(ty * 8 + r) * 16 + tx] = cp;
        red2[(ty * 8 + r) * 16 + tx] = t2acc[r];
    }
    __syncthreads();

    if (t < M_TILE) {
        float s1 = 0.0f, s2 = 0.0f;
#pragma unroll
        for (int i = 0; i < 16; i++) {
            s1 += red1[t * 16 + i];
            s2 += red2[t * 16 + i];
        }
        out[row0 + t] = 0.5f * (s1 - s2);
    }
}

extern "C" void kernel_launch(void* const* d_in, const int* in_sizes, int n_in,
                              void* d_out, int out_size) {
    const float* x = (const float*)d_in[0];   // [8192, 2048] fp32
    const float* v = (const float*)d_in[1];   // [2048, 64]   fp32
    float* out = (float*)d_out;               // [8192, 1]    fp32

    precompute_s_kernel<<<(N_DIM + 127) / 128, 128>>>(v);
    fm_kernel<<<B_ROWS / M_TILE, THREADS>>>(x, v, out);
}